// round 14
// baseline (speedup 1.0000x reference)
#include <cuda_runtime.h>
#include <cuda_fp16.h>
#include <stdint.h>
#include <math.h>

#define BATCH 4
#define NC 4096
#define NI 64
#define NT 32
#define FSH 40.0f      // exponent shift; safe since |f| <~ 75 and col-max >~ 30

// ---- static scratch ---------------------------------------------------------
__device__ __half d_theta[BATCH * NC * NI];
__device__ __half d_phi[BATCH * NC * NI];
__device__ __half d_g[BATCH * NC * NI];
__device__ __half d_wh[3 * NI * NC];          // fp16 weights [t|p|g][i][k]
__device__ float  d_Sstat[BATCH * NT * NC];   // per-n-tile col sum of exp(f-FSH)
__device__ float  d_L[BATCH * NC];            // log-normalizer FSH + ln(S)
__device__ float  d_y[BATCH * NC * NI];

// ---- helpers ----------------------------------------------------------------
__device__ __forceinline__ void mma16h(float* c, const uint32_t* a, const uint32_t* b) {
    asm volatile(
        "mma.sync.aligned.m16n8k16.row.col.f32.f16.f16.f32 "
        "{%0,%1,%2,%3},{%4,%5,%6,%7},{%8,%9},{%0,%1,%2,%3};"
        : "+f"(c[0]), "+f"(c[1]), "+f"(c[2]), "+f"(c[3])
        : "r"(a[0]), "r"(a[1]), "r"(a[2]), "r"(a[3]), "r"(b[0]), "r"(b[1]));
}
__device__ __forceinline__ uint32_t smemU32(const void* p) {
    return (uint32_t)__cvta_generic_to_shared(p);
}
__device__ __forceinline__ uint32_t packh2(float lo, float hi) {
    __half2 h = __floats2half2_rn(lo, hi);
    return *(uint32_t*)&h;
}
__device__ __forceinline__ void ldsm4(uint32_t& r0, uint32_t& r1, uint32_t& r2,
                                      uint32_t& r3, uint32_t a) {
    asm volatile("ldmatrix.sync.aligned.m8n8.x4.shared.b16 {%0,%1,%2,%3}, [%4];"
                 : "=r"(r0), "=r"(r1), "=r"(r2), "=r"(r3) : "r"(a));
}
__device__ __forceinline__ void ldsm4t(uint32_t& r0, uint32_t& r1, uint32_t& r2,
                                       uint32_t& r3, uint32_t a) {
    asm volatile("ldmatrix.sync.aligned.m8n8.x4.trans.shared.b16 {%0,%1,%2,%3}, [%4];"
                 : "=r"(r0), "=r"(r1), "=r"(r2), "=r"(r3) : "r"(a));
}

// =============================================================================
// K0: one-shot weight conversion fp32 -> fp16 (3 x 64 x 4096 elems).
// =============================================================================
__global__ __launch_bounds__(256) void k0_prep(
    const float* __restrict__ w_t, const float* __restrict__ w_p,
    const float* __restrict__ w_g)
{
    int idx = blockIdx.x * 256 + threadIdx.x;       // one float4 per thread
    const int per = NI * NC / 4;                    // 65536
    int proj = idx / per, off = idx % per;
    const float* src = (proj == 0) ? w_t : (proj == 1) ? w_p : w_g;
    float4 v = ((const float4*)src)[off];
    __half2* d = (__half2*)(d_wh + (size_t)proj * NI * NC) + off * 2;
    d[0] = __floats2half2_rn(v.x, v.y);
    d[1] = __floats2half2_rn(v.z, v.w);
}

// =============================================================================
// K1: fused projections (fp16 MMA). Tile 128m x 192n, K-chunk 32.
// Weights fp16 via cp.async double buffer; x via register prefetch + cvt.
// =============================================================================
__global__ __launch_bounds__(256) void k1_proj(
    const float* __restrict__ x,
    const float* __restrict__ b_t, const float* __restrict__ b_p,
    const float* __restrict__ b_g)
{
    const int b  = blockIdx.y;
    const int m0 = blockIdx.x * 128;
    const float* xb = x + (size_t)b * NC * NC;

    __shared__ __half Ax[128 * 40];
    __shared__ __half Bw[2][192 * 40];

    const int tid = threadIdx.x;
    const int wid = tid >> 5, lane = tid & 31;
    const int grp = lane >> 2, tig = lane & 3;
    const int wm = wid >> 1, wn = wid & 1;

    float acc[2][12][4];
#pragma unroll
    for (int mf = 0; mf < 2; mf++)
#pragma unroll
        for (int nf = 0; nf < 12; nf++)
#pragma unroll
            for (int j = 0; j < 4; j++) acc[mf][nf][j] = 0.f;

    // x loader: 2 slots/thread
    int xrow[2], xkq[2];
    const float* xsrc[2];
#pragma unroll
    for (int p = 0; p < 2; p++) {
        int slot = tid + p * 256;
        xrow[p] = slot >> 2; xkq[p] = slot & 3;
        xsrc[p] = xb + (size_t)(m0 + xrow[p]) * NC + xkq[p] * 8;
    }
    // w loader: 3 slots/thread (192 rows x 4 quads)
    int wr[3], wq[3];
#pragma unroll
    for (int p = 0; p < 3; p++) {
        int slot = tid + p * 256;
        wr[p] = slot >> 2; wq[p] = slot & 3;
    }

    auto issueW = [&](int j) {
        uint32_t bd = smemU32(Bw[j & 1]);
#pragma unroll
        for (int p = 0; p < 3; p++) {
            const __half* src = d_wh + (size_t)wr[p] * NC + j * 32 + wq[p] * 8;
            asm volatile("cp.async.cg.shared.global [%0], [%1], 16;"
                         :: "r"(bd + (uint32_t)(wr[p] * 40 + wq[p] * 8) * 2), "l"(src));
        }
        asm volatile("cp.async.commit_group;");
    };

    float4 xv[2][2];
#pragma unroll
    for (int p = 0; p < 2; p++) {
        xv[p][0] = *(const float4*)(xsrc[p]);
        xv[p][1] = *(const float4*)(xsrc[p] + 4);
    }
    issueW(0);

    const uint32_t a_base = smemU32(Ax);

    for (int k0 = 0, j = 0; k0 < NC; k0 += 32, j++) {
#pragma unroll
        for (int p = 0; p < 2; p++) {
            uint32_t* d = (uint32_t*)(Ax + xrow[p] * 40 + xkq[p] * 8);
            d[0] = packh2(xv[p][0].x, xv[p][0].y);
            d[1] = packh2(xv[p][0].z, xv[p][0].w);
            d[2] = packh2(xv[p][1].x, xv[p][1].y);
            d[3] = packh2(xv[p][1].z, xv[p][1].w);
        }
        asm volatile("cp.async.wait_group 0;");
        __syncthreads();
        if (k0 + 32 < NC) {
            int kn = k0 + 32;
#pragma unroll
            for (int p = 0; p < 2; p++) {
                xv[p][0] = *(const float4*)(xsrc[p] + kn);
                xv[p][1] = *(const float4*)(xsrc[p] + kn + 4);
            }
            issueW(j + 1);
        }
        const uint32_t b_base = smemU32(Bw[j & 1]);
#pragma unroll
        for (int ks = 0; ks < 2; ks++) {
            uint32_t a[2][4];
#pragma unroll
            for (int mf = 0; mf < 2; mf++) {
                uint32_t addr = a_base +
                    (uint32_t)(wm * 32 + mf * 16 + (lane & 7) + ((lane >> 3) & 1) * 8) * 80
                    + ks * 32 + ((lane >> 4) & 1) * 16;
                ldsm4(a[mf][0], a[mf][1], a[mf][2], a[mf][3], addr);
            }
#pragma unroll
            for (int nf2 = 0; nf2 < 6; nf2++) {
                uint32_t r0, r1, r2, r3;
                uint32_t addr = b_base +
                    (uint32_t)(wn * 96 + nf2 * 16 + (lane & 7) + ((lane >> 4) & 1) * 8) * 80
                    + ks * 32 + ((lane >> 3) & 1) * 16;
                ldsm4(r0, r1, r2, r3, addr);
                uint32_t b0[2] = { r0, r1 }, b1[2] = { r2, r3 };
#pragma unroll
                for (int mf = 0; mf < 2; mf++) {
                    mma16h(acc[mf][2 * nf2],     a[mf], b0);
                    mma16h(acc[mf][2 * nf2 + 1], a[mf], b1);
                }
            }
        }
        __syncthreads();
    }

#pragma unroll
    for (int nf = 0; nf < 12; nf++) {
        int col = wn * 96 + nf * 8 + tig * 2;
        int pr = col >> 6, lc = col & 63;
        __half* outp = ((pr == 0) ? d_theta : (pr == 1) ? d_phi : d_g) + (size_t)b * NC * NI;
        const float* bias = (pr == 0) ? b_t : (pr == 1) ? b_p : b_g;
        float bi0 = bias[lc], bi1 = bias[lc + 1];
#pragma unroll
        for (int mf = 0; mf < 2; mf++) {
            int r0 = m0 + wm * 32 + mf * 16 + grp;
            *(__half2*)(outp + (size_t)r0 * NI + lc) =
                __floats2half2_rn(acc[mf][nf][0] + bi0, acc[mf][nf][1] + bi1);
            *(__half2*)(outp + (size_t)(r0 + 8) * NI + lc) =
                __floats2half2_rn(acc[mf][nf][2] + bi0, acc[mf][nf][3] + bi1);
        }
    }
}

// =============================================================================
// K2s v2: column sums of exp(f - FSH) only (no max). One block per 128-row
// n-tile; theta + A-frags cached once; phi streamed via cp.async dbl buffer.
// 8 warps = 4n x 2m; warp 32n x 64m per 128m chunk.
// =============================================================================
#define K2_SMEM (128 * 72 * 2 + 2 * 128 * 72 * 2 + 512 * 4)   // 57344 B

__global__ __launch_bounds__(256, 1) void k2_stats()
{
    const int b  = blockIdx.y;
    const int nb = blockIdx.x;
    const int n0 = nb * 128;

    extern __shared__ char sm2[];
    __half* Ts    = (__half*)sm2;                 // [128*72]
    __half* Ps0   = Ts + 128 * 72;                // [2][128*72]
    float*  statS = (float*)(Ps0 + 2 * 128 * 72); // [128*4]

    const int tid = threadIdx.x;
    const int wid = tid >> 5, lane = tid & 31;
    const int grp = lane >> 2, tig = lane & 3;
    const int wa = wid >> 1, wbm = wid & 1;

    const __half* tb = d_theta + ((size_t)b * NC + n0) * NI;
    const __half* pb = d_phi + (size_t)b * NC * NI;

    const int lr = tid >> 3, lq = tid & 7;
    auto issueP = [&](int j) {
        uint32_t pd = smemU32(Ps0 + (j & 1) * 128 * 72);
        const __half* ph = pb + (size_t)(j * 128) * NI;
#pragma unroll
        for (int p = 0; p < 4; p++) {
            int r = lr + p * 32;
            asm volatile("cp.async.cg.shared.global [%0], [%1], 16;"
                         :: "r"(pd + (uint32_t)(r * 144 + lq * 16)),
                            "l"(ph + (size_t)r * NI + lq * 8));
        }
        asm volatile("cp.async.commit_group;");
    };

    issueP(0);
#pragma unroll
    for (int p = 0; p < 4; p++) {
        int slot = tid + p * 256;
        int r = slot >> 3, q = slot & 7;
        *(uint4*)(Ts + r * 72 + q * 8) = *(const uint4*)(tb + (size_t)r * NI + q * 8);
    }
    __syncthreads();

    const uint32_t t_base = smemU32(Ts);
    uint32_t a_th[4][2][4];
#pragma unroll
    for (int ks = 0; ks < 4; ks++)
#pragma unroll
        for (int mf = 0; mf < 2; mf++) {
            uint32_t addr = t_base +
                (uint32_t)(wa * 32 + mf * 16 + (lane & 7) + ((lane >> 3) & 1) * 8) * 144
                + ks * 32 + ((lane >> 4) & 1) * 16;
            ldsm4(a_th[ks][mf][0], a_th[ks][mf][1], a_th[ks][mf][2], a_th[ks][mf][3], addr);
        }

    float* Ssb = d_Sstat + ((size_t)b * NT + nb) * NC;

    for (int j = 0; j < 32; j++) {
        if (j + 1 < 32) {
            issueP(j + 1);
            asm volatile("cp.async.wait_group 1;");
        } else {
            asm volatile("cp.async.wait_group 0;");
        }
        __syncthreads();

        const uint32_t p_base = smemU32(Ps0 + (j & 1) * 128 * 72);
        float acc[2][8][4];
#pragma unroll
        for (int mf = 0; mf < 2; mf++)
#pragma unroll
            for (int nf = 0; nf < 8; nf++)
#pragma unroll
                for (int q = 0; q < 4; q++) acc[mf][nf][q] = 0.f;

#pragma unroll
        for (int ks = 0; ks < 4; ks++) {
#pragma unroll
            for (int nf2 = 0; nf2 < 4; nf2++) {
                uint32_t r0, r1, r2, r3;
                uint32_t addr = p_base +
                    (uint32_t)(wbm * 64 + nf2 * 16 + (lane & 7) + ((lane >> 4) & 1) * 8) * 144
                    + ks * 32 + ((lane >> 3) & 1) * 16;
                ldsm4(r0, r1, r2, r3, addr);
                uint32_t b0[2] = { r0, r1 }, b1[2] = { r2, r3 };
#pragma unroll
                for (int mf = 0; mf < 2; mf++) {
                    mma16h(acc[mf][2 * nf2],     a_th[ks][mf], b0);
                    mma16h(acc[mf][2 * nf2 + 1], a_th[ks][mf], b1);
                }
            }
        }

        // column sums of exp(f - FSH) over this warp's 32 rows -> statS
#pragma unroll
        for (int nf = 0; nf < 8; nf++) {
            float s0 = 0.f, s1 = 0.f;
#pragma unroll
            for (int mf = 0; mf < 2; mf++) {
                s0 += __expf(acc[mf][nf][0] - FSH) + __expf(acc[mf][nf][2] - FSH);
                s1 += __expf(acc[mf][nf][1] - FSH) + __expf(acc[mf][nf][3] - FSH);
            }
#pragma unroll
            for (int o = 4; o <= 16; o <<= 1) {
                s0 += __shfl_xor_sync(0xffffffffu, s0, o);
                s1 += __shfl_xor_sync(0xffffffffu, s1, o);
            }
            if (grp == 0) {
                int col = wbm * 64 + nf * 8 + tig * 2;
                statS[col * 4 + wa] = s0;
                statS[(col + 1) * 4 + wa] = s1;
            }
        }
        __syncthreads();
        if (tid < 128)
            Ssb[j * 128 + tid] = (statS[tid * 4] + statS[tid * 4 + 1])
                               + (statS[tid * 4 + 2] + statS[tid * 4 + 3]);
    }
}

// =============================================================================
// K3b: L[m] = FSH + ln(sum over n-tiles of Sstat).
// =============================================================================
__global__ __launch_bounds__(256) void k3b_stats()
{
    int t = blockIdx.x * 256 + threadIdx.x;
    int b = t >> 12, m = t & (NC - 1);
    const float* Sp = d_Sstat + (size_t)b * NT * NC + m;
    float S = 0.f;
#pragma unroll
    for (int nt = 0; nt < NT; nt++) S += Sp[(size_t)nt * NC];
    d_L[(size_t)b * NC + m] = FSH + logf(S);
}

// =============================================================================
// K4 fused: y[n][i] = sum_m exp(f[n,m]-L[m]) * g[m][i]
// cp.async double-buffered phi/g/L chunks; g raw (no scaling pass).
// Block: 128 n-rows, 8 warps x 16 rows; m chunks of 128.
// =============================================================================
#define K4_SMEM (4 * 128 * 72 * 2 + 2 * 128 * 4)   // 74752 B

__global__ __launch_bounds__(256, 1) void k4_fused()
{
    const int b  = blockIdx.y;
    const int n0 = blockIdx.x * 128;

    extern __shared__ char sm4[];
    __half* Ps0 = (__half*)sm4;
    __half* Gs0 = Ps0 + 2 * 128 * 72;
    float*  Ls0 = (float*)(Gs0 + 2 * 128 * 72);

    const int tid = threadIdx.x;
    const int wid = tid >> 5, lane = tid & 31;
    const int grp = lane >> 2, tig = lane & 3;
    const int lane15 = lane & 15, lanehi = (lane >> 4) & 1;

    const __half* thb = d_theta + ((size_t)b * NC + n0) * NI;
    const __half* phb = d_phi + (size_t)b * NC * NI;
    const __half* gb  = d_g   + (size_t)b * NC * NI;
    const float*  Lb  = d_L   + (size_t)b * NC;

    // stage theta (buffer 0), grab A-fragments
#pragma unroll
    for (int p = 0; p < 4; p++) {
        int slot = tid + p * 256;
        int r = slot >> 3, q = slot & 7;
        *(uint4*)(Ps0 + r * 72 + q * 8) = *(const uint4*)(thb + (size_t)r * NI + q * 8);
    }
    __syncthreads();
    uint32_t a_th[4][4];
#pragma unroll
    for (int ks = 0; ks < 4; ks++) {
        uint32_t addr = smemU32(Ps0) +
            (uint32_t)(wid * 16 + (lane & 7) + ((lane >> 3) & 1) * 8) * 144
            + ks * 32 + ((lane >> 4) & 1) * 16;
        ldsm4(a_th[ks][0], a_th[ks][1], a_th[ks][2], a_th[ks][3], addr);
    }
    __syncthreads();

    float yacc[8][4];
#pragma unroll
    for (int ib = 0; ib < 8; ib++)
#pragma unroll
        for (int j = 0; j < 4; j++) yacc[ib][j] = 0.f;

    const int lr = tid >> 3, lq = tid & 7;
    auto issue = [&](int j) {
        int buf = j & 1;
        const __half* ph = phb + (size_t)(j * 128) * NI;
        const __half* gh = gb  + (size_t)(j * 128) * NI;
        uint32_t pd = smemU32(Ps0 + buf * 128 * 72);
        uint32_t gd = smemU32(Gs0 + buf * 128 * 72);
#pragma unroll
        for (int p = 0; p < 4; p++) {
            int r = lr + p * 32;
            asm volatile("cp.async.cg.shared.global [%0], [%1], 16;"
                         :: "r"(pd + (uint32_t)(r * 144 + lq * 16)),
                            "l"(ph + (size_t)r * NI + lq * 8));
            asm volatile("cp.async.cg.shared.global [%0], [%1], 16;"
                         :: "r"(gd + (uint32_t)(r * 144 + lq * 16)),
                            "l"(gh + (size_t)r * NI + lq * 8));
        }
        if (tid < 32)
            asm volatile("cp.async.cg.shared.global [%0], [%1], 16;"
                         :: "r"(smemU32(Ls0 + buf * 128) + tid * 16),
                            "l"(Lb + j * 128 + tid * 4));
        asm volatile("cp.async.commit_group;");
    };

    issue(0);
    for (int j = 0; j < 32; j++) {
        if (j + 1 < 32) {
            issue(j + 1);
            asm volatile("cp.async.wait_group 1;");
        } else {
            asm volatile("cp.async.wait_group 0;");
        }
        __syncthreads();

        int buf = j & 1;
        const uint32_t p_base = smemU32(Ps0 + buf * 128 * 72);
        const uint32_t g_base = smemU32(Gs0 + buf * 128 * 72);
        const float* Lsm = Ls0 + buf * 128;

#pragma unroll
        for (int c = 0; c < 8; c += 2) {
            float fa[2][2][4];
#pragma unroll
            for (int cc = 0; cc < 2; cc++)
#pragma unroll
                for (int jj = 0; jj < 2; jj++)
#pragma unroll
                    for (int q = 0; q < 4; q++) fa[cc][jj][q] = 0.f;

#pragma unroll
            for (int cc = 0; cc < 2; cc++) {
#pragma unroll
                for (int ks = 0; ks < 4; ks++) {
                    uint32_t r0, r1, r2, r3;
                    uint32_t addr = p_base +
                        (uint32_t)((c + cc) * 16 + (lane & 7) + ((lane >> 4) & 1) * 8) * 144
                        + ks * 32 + ((lane >> 3) & 1) * 16;
                    ldsm4(r0, r1, r2, r3, addr);
                    uint32_t b0[2] = { r0, r1 }, b1[2] = { r2, r3 };
                    mma16h(fa[cc][0], a_th[ks], b0);
                    mma16h(fa[cc][1], a_th[ks], b1);
                }
            }
            uint32_t ap[2][4];
#pragma unroll
            for (int cc = 0; cc < 2; cc++) {
                int cb = (c + cc) * 16;
                float M0 = Lsm[cb + tig * 2],     M1 = Lsm[cb + tig * 2 + 1];
                float M2 = Lsm[cb + 8 + tig * 2], M3 = Lsm[cb + 8 + tig * 2 + 1];
                ap[cc][0] = packh2(__expf(fa[cc][0][0] - M0), __expf(fa[cc][0][1] - M1));
                ap[cc][1] = packh2(__expf(fa[cc][0][2] - M0), __expf(fa[cc][0][3] - M1));
                ap[cc][2] = packh2(__expf(fa[cc][1][0] - M2), __expf(fa[cc][1][1] - M3));
                ap[cc][3] = packh2(__expf(fa[cc][1][2] - M2), __expf(fa[cc][1][3] - M3));
            }
#pragma unroll
            for (int cc = 0; cc < 2; cc++) {
#pragma unroll
                for (int ib = 0; ib < 4; ib++) {
                    uint32_t r0, r1, r2, r3;
                    uint32_t addr = g_base +
                        ((uint32_t)(((c + cc) * 16 + lane15) * 72 + ib * 16 + lanehi * 8)) * 2;
                    ldsm4t(r0, r1, r2, r3, addr);
                    uint32_t b0[2] = { r0, r1 }, b1[2] = { r2, r3 };
                    mma16h(yacc[2 * ib],     ap[cc], b0);
                    mma16h(yacc[2 * ib + 1], ap[cc], b1);
                }
            }
        }
        __syncthreads();
    }

    float* yp = d_y + ((size_t)b * NC + n0 + wid * 16 + grp) * NI;
#pragma unroll
    for (int ib = 0; ib < 8; ib++) {
        int i = ib * 8 + tig * 2;
        *(float2*)(yp + i)          = make_float2(yacc[ib][0], yacc[ib][1]);
        *(float2*)(yp + 8 * NI + i) = make_float2(yacc[ib][2], yacc[ib][3]);
    }
}

// =============================================================================
// K5 (fp16 MMA, cp.async-overlapped residual) — now 2 CTAs/SM.
// =============================================================================
#define K5_SMEM ((128 * 72 + 64 * 72) * 2 + 64 * 132 * 4)   // 61440 B

__global__ __launch_bounds__(256, 2) void k5_out(
    const float* __restrict__ x, const float* __restrict__ Ww,
    const float* __restrict__ Wb, float* __restrict__ out)
{
    const int b  = blockIdx.z;
    const int a0 = blockIdx.y * 128;
    const int d0 = blockIdx.x * 64;

    extern __shared__ char sm5[];
    __half* As = (__half*)sm5;
    __half* Bs = As + 128 * 72;
    float*  Xs = (float*)(sm5 + (128 * 72 + 64 * 72) * 2);

    const int tid = threadIdx.x;
    const int wid = tid >> 5, lane = tid & 31;
    const int grp = lane >> 2, tig = lane & 3;
    const int wa = wid >> 1, wd = wid & 1;

    const float* xb = x + (size_t)b * NC * NC;
    const uint32_t xs_base = smemU32(Xs);

#pragma unroll
    for (int p = 0; p < 8; p++) {
        int slot = tid + p * 256;
        int dl = slot >> 5, q = slot & 31;
        const float* src = xb + (size_t)(d0 + dl) * NC + a0 + q * 4;
        uint32_t dst = xs_base + (uint32_t)(dl * 132 + q * 4) * 4;
        asm volatile("cp.async.cg.shared.global [%0], [%1], 16;" :: "r"(dst), "l"(src));
    }
    asm volatile("cp.async.commit_group;");

#pragma unroll
    for (int p = 0; p < 8; p++) {
        int slot = tid + p * 256;
        int r = slot >> 4, q = slot & 15;
        float4 v = *(const float4*)(Ww + (size_t)(a0 + r) * NI + q * 4);
        uint32_t* d = (uint32_t*)(As + r * 72 + q * 4);
        d[0] = packh2(v.x, v.y); d[1] = packh2(v.z, v.w);
    }
#pragma unroll
    for (int p = 0; p < 4; p++) {
        int slot = tid + p * 256;
        int r = slot >> 4, q = slot & 15;
        float4 v = *(const float4*)(d_y + ((size_t)b * NC + d0 + r) * NI + q * 4);
        uint32_t* d = (uint32_t*)(Bs + r * 72 + q * 4);
        d[0] = packh2(v.x, v.y); d[1] = packh2(v.z, v.w);
    }
    __syncthreads();

    const uint32_t a_base = smemU32(As);
    const uint32_t b_base = smemU32(Bs);
    float acc[2][4][4];
#pragma unroll
    for (int mf = 0; mf < 2; mf++)
#pragma unroll
        for (int nf = 0; nf < 4; nf++)
#pragma unroll
            for (int j = 0; j < 4; j++) acc[mf][nf][j] = 0.f;

#pragma unroll
    for (int ks = 0; ks < 4; ks++) {
        uint32_t a[2][4];
#pragma unroll
        for (int mf = 0; mf < 2; mf++) {
            uint32_t addr = a_base +
                (uint32_t)(wa * 32 + mf * 16 + (lane & 7) + ((lane >> 3) & 1) * 8) * 144
                + ks * 32 + ((lane >> 4) & 1) * 16;
            ldsm4(a[mf][0], a[mf][1], a[mf][2], a[mf][3], addr);
        }
#pragma unroll
        for (int nf2 = 0; nf2 < 2; nf2++) {
            uint32_t r0, r1, r2, r3;
            uint32_t addr = b_base +
                (uint32_t)(wd * 32 + nf2 * 16 + (lane & 7) + ((lane >> 4) & 1) * 8) * 144
                + ks * 32 + ((lane >> 3) & 1) * 16;
            ldsm4(r0, r1, r2, r3, addr);
            uint32_t b0[2] = { r0, r1 }, b1[2] = { r2, r3 };
#pragma unroll
            for (int mf = 0; mf < 2; mf++) {
                mma16h(acc[mf][2 * nf2],     a[mf], b0);
                mma16h(acc[mf][2 * nf2 + 1], a[mf], b1);
            }
        }
    }

    asm volatile("cp.async.wait_group 0;");
    __syncthreads();

    float* ob = out + (size_t)b * NC * NC;
#pragma unroll
    for (int mf = 0; mf < 2; mf++)
#pragma unroll
        for (int h = 0; h < 2; h++) {
            int al = wa * 32 + mf * 16 + grp + 8 * h;
            int a  = a0 + al;
            float wb_ = Wb[a];
#pragma unroll
            for (int nf = 0; nf < 4; nf++) {
                int d = wd * 32 + nf * 8 + tig * 2;
                float r0 = Xs[d * 132 + al];
                float r1 = Xs[(d + 1) * 132 + al];
                *(float2*)(ob + (size_t)a * NC + d0 + d) =
                    make_float2(acc[mf][nf][2 * h] + wb_ + r0,
                                acc[mf][nf][2 * h + 1] + wb_ + r1);
            }
        }
}

// =============================================================================
extern "C" void kernel_launch(void* const* d_in, const int* in_sizes, int n_in,
                              void* d_out, int out_size)
{
    (void)in_sizes; (void)n_in; (void)out_size;
    const float* x   = (const float*)d_in[0];
    const float* g_w = (const float*)d_in[1];
    const float* g_b = (const float*)d_in[2];
    const float* t_w = (const float*)d_in[3];
    const float* t_b = (const float*)d_in[4];
    const float* p_w = (const float*)d_in[5];
    const float* p_b = (const float*)d_in[6];
    const float* W_w = (const float*)d_in[7];
    const float* W_b = (const float*)d_in[8];
    float* out = (float*)d_out;

    static int attr_set = 0;
    if (!attr_set) {
        cudaFuncSetAttribute(k2_stats, cudaFuncAttributeMaxDynamicSharedMemorySize, K2_SMEM);
        cudaFuncSetAttribute(k4_fused, cudaFuncAttributeMaxDynamicSharedMemorySize, K4_SMEM);
        cudaFuncSetAttribute(k5_out, cudaFuncAttributeMaxDynamicSharedMemorySize, K5_SMEM);
        attr_set = 1;
    }

    k0_prep  <<<3 * NI * NC / 4 / 256, 256>>>(t_w, p_w, g_w);
    k1_proj  <<<dim3(NC / 128, BATCH), 256>>>(x, t_b, p_b, g_b);
    k2_stats <<<dim3(NC / 128, BATCH), 256, K2_SMEM>>>();
    k3b_stats<<<BATCH * NC / 256, 256>>>();
    k4_fused <<<dim3(NC / 128, BATCH), 256, K4_SMEM>>>();
    k5_out   <<<dim3(NC / 64, NC / 128, BATCH), 256, K5_SMEM>>>(x, W_w, W_b, out);
}

// round 15
// speedup vs baseline: 1.0319x; 1.0319x over previous
#include <cuda_runtime.h>
#include <cuda_fp16.h>
#include <stdint.h>
#include <math.h>

#define BATCH 4
#define NC 4096
#define NI 64
#define NT 32
#define FSH 40.0f      // exponent shift; safe since |f| <~ 75 and col-max >~ 30

// ---- static scratch ---------------------------------------------------------
__device__ __half d_theta[BATCH * NC * NI];
__device__ __half d_phi[BATCH * NC * NI];
__device__ __half d_g[BATCH * NC * NI];
__device__ __half d_wh[3 * NI * NC];          // fp16 weights [t|p|g][i][k]
__device__ float  d_Sstat[BATCH * NT * NC];   // per-n-tile col sum of exp(f-FSH)
__device__ float  d_L[BATCH * NC];            // log-normalizer FSH + ln(S)
__device__ __half d_y16[BATCH * NC * NI];     // y fp16 (k5 rounds to fp16 anyway)

// ---- helpers ----------------------------------------------------------------
__device__ __forceinline__ void mma16h(float* c, const uint32_t* a, const uint32_t* b) {
    asm volatile(
        "mma.sync.aligned.m16n8k16.row.col.f32.f16.f16.f32 "
        "{%0,%1,%2,%3},{%4,%5,%6,%7},{%8,%9},{%0,%1,%2,%3};"
        : "+f"(c[0]), "+f"(c[1]), "+f"(c[2]), "+f"(c[3])
        : "r"(a[0]), "r"(a[1]), "r"(a[2]), "r"(a[3]), "r"(b[0]), "r"(b[1]));
}
__device__ __forceinline__ uint32_t smemU32(const void* p) {
    return (uint32_t)__cvta_generic_to_shared(p);
}
__device__ __forceinline__ uint32_t packh2(float lo, float hi) {
    __half2 h = __floats2half2_rn(lo, hi);
    return *(uint32_t*)&h;
}
__device__ __forceinline__ void ldsm4(uint32_t& r0, uint32_t& r1, uint32_t& r2,
                                      uint32_t& r3, uint32_t a) {
    asm volatile("ldmatrix.sync.aligned.m8n8.x4.shared.b16 {%0,%1,%2,%3}, [%4];"
                 : "=r"(r0), "=r"(r1), "=r"(r2), "=r"(r3) : "r"(a));
}
__device__ __forceinline__ void ldsm4t(uint32_t& r0, uint32_t& r1, uint32_t& r2,
                                       uint32_t& r3, uint32_t a) {
    asm volatile("ldmatrix.sync.aligned.m8n8.x4.trans.shared.b16 {%0,%1,%2,%3}, [%4];"
                 : "=r"(r0), "=r"(r1), "=r"(r2), "=r"(r3) : "r"(a));
}

// =============================================================================
// K0: one-shot weight conversion fp32 -> fp16 (3 x 64 x 4096 elems).
// =============================================================================
__global__ __launch_bounds__(256) void k0_prep(
    const float* __restrict__ w_t, const float* __restrict__ w_p,
    const float* __restrict__ w_g)
{
    int idx = blockIdx.x * 256 + threadIdx.x;       // one float4 per thread
    const int per = NI * NC / 4;                    // 65536
    int proj = idx / per, off = idx % per;
    const float* src = (proj == 0) ? w_t : (proj == 1) ? w_p : w_g;
    float4 v = ((const float4*)src)[off];
    __half2* d = (__half2*)(d_wh + (size_t)proj * NI * NC) + off * 2;
    d[0] = __floats2half2_rn(v.x, v.y);
    d[1] = __floats2half2_rn(v.z, v.w);
}

// =============================================================================
// K1: fused projections (fp16 MMA). Tile 128m x 192n, K-chunk 32.
// Weights fp16 via cp.async double buffer; x via register prefetch + cvt.
// =============================================================================
__global__ __launch_bounds__(256) void k1_proj(
    const float* __restrict__ x,
    const float* __restrict__ b_t, const float* __restrict__ b_p,
    const float* __restrict__ b_g)
{
    const int b  = blockIdx.y;
    const int m0 = blockIdx.x * 128;
    const float* xb = x + (size_t)b * NC * NC;

    __shared__ __half Ax[128 * 40];
    __shared__ __half Bw[2][192 * 40];

    const int tid = threadIdx.x;
    const int wid = tid >> 5, lane = tid & 31;
    const int grp = lane >> 2, tig = lane & 3;
    const int wm = wid >> 1, wn = wid & 1;

    float acc[2][12][4];
#pragma unroll
    for (int mf = 0; mf < 2; mf++)
#pragma unroll
        for (int nf = 0; nf < 12; nf++)
#pragma unroll
            for (int j = 0; j < 4; j++) acc[mf][nf][j] = 0.f;

    // x loader: 2 slots/thread
    int xrow[2], xkq[2];
    const float* xsrc[2];
#pragma unroll
    for (int p = 0; p < 2; p++) {
        int slot = tid + p * 256;
        xrow[p] = slot >> 2; xkq[p] = slot & 3;
        xsrc[p] = xb + (size_t)(m0 + xrow[p]) * NC + xkq[p] * 8;
    }
    // w loader: 3 slots/thread (192 rows x 4 quads)
    int wr[3], wq[3];
#pragma unroll
    for (int p = 0; p < 3; p++) {
        int slot = tid + p * 256;
        wr[p] = slot >> 2; wq[p] = slot & 3;
    }

    auto issueW = [&](int j) {
        uint32_t bd = smemU32(Bw[j & 1]);
#pragma unroll
        for (int p = 0; p < 3; p++) {
            const __half* src = d_wh + (size_t)wr[p] * NC + j * 32 + wq[p] * 8;
            asm volatile("cp.async.cg.shared.global [%0], [%1], 16;"
                         :: "r"(bd + (uint32_t)(wr[p] * 40 + wq[p] * 8) * 2), "l"(src));
        }
        asm volatile("cp.async.commit_group;");
    };

    float4 xv[2][2];
#pragma unroll
    for (int p = 0; p < 2; p++) {
        xv[p][0] = *(const float4*)(xsrc[p]);
        xv[p][1] = *(const float4*)(xsrc[p] + 4);
    }
    issueW(0);

    const uint32_t a_base = smemU32(Ax);

    for (int k0 = 0, j = 0; k0 < NC; k0 += 32, j++) {
#pragma unroll
        for (int p = 0; p < 2; p++) {
            uint32_t* d = (uint32_t*)(Ax + xrow[p] * 40 + xkq[p] * 8);
            d[0] = packh2(xv[p][0].x, xv[p][0].y);
            d[1] = packh2(xv[p][0].z, xv[p][0].w);
            d[2] = packh2(xv[p][1].x, xv[p][1].y);
            d[3] = packh2(xv[p][1].z, xv[p][1].w);
        }
        asm volatile("cp.async.wait_group 0;");
        __syncthreads();
        if (k0 + 32 < NC) {
            int kn = k0 + 32;
#pragma unroll
            for (int p = 0; p < 2; p++) {
                xv[p][0] = *(const float4*)(xsrc[p] + kn);
                xv[p][1] = *(const float4*)(xsrc[p] + kn + 4);
            }
            issueW(j + 1);
        }
        const uint32_t b_base = smemU32(Bw[j & 1]);
#pragma unroll
        for (int ks = 0; ks < 2; ks++) {
            uint32_t a[2][4];
#pragma unroll
            for (int mf = 0; mf < 2; mf++) {
                uint32_t addr = a_base +
                    (uint32_t)(wm * 32 + mf * 16 + (lane & 7) + ((lane >> 3) & 1) * 8) * 80
                    + ks * 32 + ((lane >> 4) & 1) * 16;
                ldsm4(a[mf][0], a[mf][1], a[mf][2], a[mf][3], addr);
            }
#pragma unroll
            for (int nf2 = 0; nf2 < 6; nf2++) {
                uint32_t r0, r1, r2, r3;
                uint32_t addr = b_base +
                    (uint32_t)(wn * 96 + nf2 * 16 + (lane & 7) + ((lane >> 4) & 1) * 8) * 80
                    + ks * 32 + ((lane >> 3) & 1) * 16;
                ldsm4(r0, r1, r2, r3, addr);
                uint32_t b0[2] = { r0, r1 }, b1[2] = { r2, r3 };
#pragma unroll
                for (int mf = 0; mf < 2; mf++) {
                    mma16h(acc[mf][2 * nf2],     a[mf], b0);
                    mma16h(acc[mf][2 * nf2 + 1], a[mf], b1);
                }
            }
        }
        __syncthreads();
    }

#pragma unroll
    for (int nf = 0; nf < 12; nf++) {
        int col = wn * 96 + nf * 8 + tig * 2;
        int pr = col >> 6, lc = col & 63;
        __half* outp = ((pr == 0) ? d_theta : (pr == 1) ? d_phi : d_g) + (size_t)b * NC * NI;
        const float* bias = (pr == 0) ? b_t : (pr == 1) ? b_p : b_g;
        float bi0 = bias[lc], bi1 = bias[lc + 1];
#pragma unroll
        for (int mf = 0; mf < 2; mf++) {
            int r0 = m0 + wm * 32 + mf * 16 + grp;
            *(__half2*)(outp + (size_t)r0 * NI + lc) =
                __floats2half2_rn(acc[mf][nf][0] + bi0, acc[mf][nf][1] + bi1);
            *(__half2*)(outp + (size_t)(r0 + 8) * NI + lc) =
                __floats2half2_rn(acc[mf][nf][2] + bi0, acc[mf][nf][3] + bi1);
        }
    }
}

// =============================================================================
// K2s v2: column sums of exp(f - FSH) only (no max). One block per 128-row
// n-tile; theta + A-frags cached once; phi streamed via cp.async dbl buffer.
// 8 warps = 4n x 2m; warp 32n x 64m per 128m chunk.
// =============================================================================
#define K2_SMEM (128 * 72 * 2 + 2 * 128 * 72 * 2 + 512 * 4)   // 57344 B

__global__ __launch_bounds__(256, 1) void k2_stats()
{
    const int b  = blockIdx.y;
    const int nb = blockIdx.x;
    const int n0 = nb * 128;

    extern __shared__ char sm2[];
    __half* Ts    = (__half*)sm2;                 // [128*72]
    __half* Ps0   = Ts + 128 * 72;                // [2][128*72]
    float*  statS = (float*)(Ps0 + 2 * 128 * 72); // [128*4]

    const int tid = threadIdx.x;
    const int wid = tid >> 5, lane = tid & 31;
    const int grp = lane >> 2, tig = lane & 3;
    const int wa = wid >> 1, wbm = wid & 1;

    const __half* tb = d_theta + ((size_t)b * NC + n0) * NI;
    const __half* pb = d_phi + (size_t)b * NC * NI;

    const int lr = tid >> 3, lq = tid & 7;
    auto issueP = [&](int j) {
        uint32_t pd = smemU32(Ps0 + (j & 1) * 128 * 72);
        const __half* ph = pb + (size_t)(j * 128) * NI;
#pragma unroll
        for (int p = 0; p < 4; p++) {
            int r = lr + p * 32;
            asm volatile("cp.async.cg.shared.global [%0], [%1], 16;"
                         :: "r"(pd + (uint32_t)(r * 144 + lq * 16)),
                            "l"(ph + (size_t)r * NI + lq * 8));
        }
        asm volatile("cp.async.commit_group;");
    };

    issueP(0);
#pragma unroll
    for (int p = 0; p < 4; p++) {
        int slot = tid + p * 256;
        int r = slot >> 3, q = slot & 7;
        *(uint4*)(Ts + r * 72 + q * 8) = *(const uint4*)(tb + (size_t)r * NI + q * 8);
    }
    __syncthreads();

    const uint32_t t_base = smemU32(Ts);
    uint32_t a_th[4][2][4];
#pragma unroll
    for (int ks = 0; ks < 4; ks++)
#pragma unroll
        for (int mf = 0; mf < 2; mf++) {
            uint32_t addr = t_base +
                (uint32_t)(wa * 32 + mf * 16 + (lane & 7) + ((lane >> 3) & 1) * 8) * 144
                + ks * 32 + ((lane >> 4) & 1) * 16;
            ldsm4(a_th[ks][mf][0], a_th[ks][mf][1], a_th[ks][mf][2], a_th[ks][mf][3], addr);
        }

    float* Ssb = d_Sstat + ((size_t)b * NT + nb) * NC;

    for (int j = 0; j < 32; j++) {
        if (j + 1 < 32) {
            issueP(j + 1);
            asm volatile("cp.async.wait_group 1;");
        } else {
            asm volatile("cp.async.wait_group 0;");
        }
        __syncthreads();

        const uint32_t p_base = smemU32(Ps0 + (j & 1) * 128 * 72);
        float acc[2][8][4];
#pragma unroll
        for (int mf = 0; mf < 2; mf++)
#pragma unroll
            for (int nf = 0; nf < 8; nf++)
#pragma unroll
                for (int q = 0; q < 4; q++) acc[mf][nf][q] = 0.f;

#pragma unroll
        for (int ks = 0; ks < 4; ks++) {
#pragma unroll
            for (int nf2 = 0; nf2 < 4; nf2++) {
                uint32_t r0, r1, r2, r3;
                uint32_t addr = p_base +
                    (uint32_t)(wbm * 64 + nf2 * 16 + (lane & 7) + ((lane >> 4) & 1) * 8) * 144
                    + ks * 32 + ((lane >> 3) & 1) * 16;
                ldsm4(r0, r1, r2, r3, addr);
                uint32_t b0[2] = { r0, r1 }, b1[2] = { r2, r3 };
#pragma unroll
                for (int mf = 0; mf < 2; mf++) {
                    mma16h(acc[mf][2 * nf2],     a_th[ks][mf], b0);
                    mma16h(acc[mf][2 * nf2 + 1], a_th[ks][mf], b1);
                }
            }
        }

        // column sums of exp(f - FSH) over this warp's 32 rows -> statS
#pragma unroll
        for (int nf = 0; nf < 8; nf++) {
            float s0 = 0.f, s1 = 0.f;
#pragma unroll
            for (int mf = 0; mf < 2; mf++) {
                s0 += __expf(acc[mf][nf][0] - FSH) + __expf(acc[mf][nf][2] - FSH);
                s1 += __expf(acc[mf][nf][1] - FSH) + __expf(acc[mf][nf][3] - FSH);
            }
#pragma unroll
            for (int o = 4; o <= 16; o <<= 1) {
                s0 += __shfl_xor_sync(0xffffffffu, s0, o);
                s1 += __shfl_xor_sync(0xffffffffu, s1, o);
            }
            if (grp == 0) {
                int col = wbm * 64 + nf * 8 + tig * 2;
                statS[col * 4 + wa] = s0;
                statS[(col + 1) * 4 + wa] = s1;
            }
        }
        __syncthreads();
        if (tid < 128)
            Ssb[j * 128 + tid] = (statS[tid * 4] + statS[tid * 4 + 1])
                               + (statS[tid * 4 + 2] + statS[tid * 4 + 3]);
    }
}

// =============================================================================
// K3b: L[m] = FSH + ln(sum over n-tiles of Sstat).
// =============================================================================
__global__ __launch_bounds__(256) void k3b_stats()
{
    int t = blockIdx.x * 256 + threadIdx.x;
    int b = t >> 12, m = t & (NC - 1);
    const float* Sp = d_Sstat + (size_t)b * NT * NC + m;
    float S = 0.f;
#pragma unroll
    for (int nt = 0; nt < NT; nt++) S += Sp[(size_t)nt * NC];
    d_L[(size_t)b * NC + m] = FSH + logf(S);
}

// =============================================================================
// K4 fused: y[n][i] = sum_m exp(f[n,m]-L[m]) * g[m][i]
// cp.async double-buffered phi/g/L chunks; g raw (no scaling pass).
// Block: 128 n-rows, 8 warps x 16 rows; m chunks of 128. y stored fp16.
// =============================================================================
#define K4_SMEM (4 * 128 * 72 * 2 + 2 * 128 * 4)   // 74752 B

__global__ __launch_bounds__(256, 1) void k4_fused()
{
    const int b  = blockIdx.y;
    const int n0 = blockIdx.x * 128;

    extern __shared__ char sm4[];
    __half* Ps0 = (__half*)sm4;
    __half* Gs0 = Ps0 + 2 * 128 * 72;
    float*  Ls0 = (float*)(Gs0 + 2 * 128 * 72);

    const int tid = threadIdx.x;
    const int wid = tid >> 5, lane = tid & 31;
    const int grp = lane >> 2, tig = lane & 3;
    const int lane15 = lane & 15, lanehi = (lane >> 4) & 1;

    const __half* thb = d_theta + ((size_t)b * NC + n0) * NI;
    const __half* phb = d_phi + (size_t)b * NC * NI;
    const __half* gb  = d_g   + (size_t)b * NC * NI;
    const float*  Lb  = d_L   + (size_t)b * NC;

    // stage theta (buffer 0), grab A-fragments
#pragma unroll
    for (int p = 0; p < 4; p++) {
        int slot = tid + p * 256;
        int r = slot >> 3, q = slot & 7;
        *(uint4*)(Ps0 + r * 72 + q * 8) = *(const uint4*)(thb + (size_t)r * NI + q * 8);
    }
    __syncthreads();
    uint32_t a_th[4][4];
#pragma unroll
    for (int ks = 0; ks < 4; ks++) {
        uint32_t addr = smemU32(Ps0) +
            (uint32_t)(wid * 16 + (lane & 7) + ((lane >> 3) & 1) * 8) * 144
            + ks * 32 + ((lane >> 4) & 1) * 16;
        ldsm4(a_th[ks][0], a_th[ks][1], a_th[ks][2], a_th[ks][3], addr);
    }
    __syncthreads();

    float yacc[8][4];
#pragma unroll
    for (int ib = 0; ib < 8; ib++)
#pragma unroll
        for (int j = 0; j < 4; j++) yacc[ib][j] = 0.f;

    const int lr = tid >> 3, lq = tid & 7;
    auto issue = [&](int j) {
        int buf = j & 1;
        const __half* ph = phb + (size_t)(j * 128) * NI;
        const __half* gh = gb  + (size_t)(j * 128) * NI;
        uint32_t pd = smemU32(Ps0 + buf * 128 * 72);
        uint32_t gd = smemU32(Gs0 + buf * 128 * 72);
#pragma unroll
        for (int p = 0; p < 4; p++) {
            int r = lr + p * 32;
            asm volatile("cp.async.cg.shared.global [%0], [%1], 16;"
                         :: "r"(pd + (uint32_t)(r * 144 + lq * 16)),
                            "l"(ph + (size_t)r * NI + lq * 8));
            asm volatile("cp.async.cg.shared.global [%0], [%1], 16;"
                         :: "r"(gd + (uint32_t)(r * 144 + lq * 16)),
                            "l"(gh + (size_t)r * NI + lq * 8));
        }
        if (tid < 32)
            asm volatile("cp.async.cg.shared.global [%0], [%1], 16;"
                         :: "r"(smemU32(Ls0 + buf * 128) + tid * 16),
                            "l"(Lb + j * 128 + tid * 4));
        asm volatile("cp.async.commit_group;");
    };

    issue(0);
    for (int j = 0; j < 32; j++) {
        if (j + 1 < 32) {
            issue(j + 1);
            asm volatile("cp.async.wait_group 1;");
        } else {
            asm volatile("cp.async.wait_group 0;");
        }
        __syncthreads();

        int buf = j & 1;
        const uint32_t p_base = smemU32(Ps0 + buf * 128 * 72);
        const uint32_t g_base = smemU32(Gs0 + buf * 128 * 72);
        const float* Lsm = Ls0 + buf * 128;

#pragma unroll
        for (int c = 0; c < 8; c += 2) {
            float fa[2][2][4];
#pragma unroll
            for (int cc = 0; cc < 2; cc++)
#pragma unroll
                for (int jj = 0; jj < 2; jj++)
#pragma unroll
                    for (int q = 0; q < 4; q++) fa[cc][jj][q] = 0.f;

#pragma unroll
            for (int cc = 0; cc < 2; cc++) {
#pragma unroll
                for (int ks = 0; ks < 4; ks++) {
                    uint32_t r0, r1, r2, r3;
                    uint32_t addr = p_base +
                        (uint32_t)((c + cc) * 16 + (lane & 7) + ((lane >> 4) & 1) * 8) * 144
                        + ks * 32 + ((lane >> 3) & 1) * 16;
                    ldsm4(r0, r1, r2, r3, addr);
                    uint32_t b0[2] = { r0, r1 }, b1[2] = { r2, r3 };
                    mma16h(fa[cc][0], a_th[ks], b0);
                    mma16h(fa[cc][1], a_th[ks], b1);
                }
            }
            uint32_t ap[2][4];
#pragma unroll
            for (int cc = 0; cc < 2; cc++) {
                int cb = (c + cc) * 16;
                float M0 = Lsm[cb + tig * 2],     M1 = Lsm[cb + tig * 2 + 1];
                float M2 = Lsm[cb + 8 + tig * 2], M3 = Lsm[cb + 8 + tig * 2 + 1];
                ap[cc][0] = packh2(__expf(fa[cc][0][0] - M0), __expf(fa[cc][0][1] - M1));
                ap[cc][1] = packh2(__expf(fa[cc][0][2] - M0), __expf(fa[cc][0][3] - M1));
                ap[cc][2] = packh2(__expf(fa[cc][1][0] - M2), __expf(fa[cc][1][1] - M3));
                ap[cc][3] = packh2(__expf(fa[cc][1][2] - M2), __expf(fa[cc][1][3] - M3));
            }
#pragma unroll
            for (int cc = 0; cc < 2; cc++) {
#pragma unroll
                for (int ib = 0; ib < 4; ib++) {
                    uint32_t r0, r1, r2, r3;
                    uint32_t addr = g_base +
                        ((uint32_t)(((c + cc) * 16 + lane15) * 72 + ib * 16 + lanehi * 8)) * 2;
                    ldsm4t(r0, r1, r2, r3, addr);
                    uint32_t b0[2] = { r0, r1 }, b1[2] = { r2, r3 };
                    mma16h(yacc[2 * ib],     ap[cc], b0);
                    mma16h(yacc[2 * ib + 1], ap[cc], b1);
                }
            }
        }
        __syncthreads();
    }

    __half* yp = d_y16 + ((size_t)b * NC + n0 + wid * 16 + grp) * NI;
#pragma unroll
    for (int ib = 0; ib < 8; ib++) {
        int i = ib * 8 + tig * 2;
        *(__half2*)(yp + i)          = __floats2half2_rn(yacc[ib][0], yacc[ib][1]);
        *(__half2*)(yp + 8 * NI + i) = __floats2half2_rn(yacc[ib][2], yacc[ib][3]);
    }
}

// =============================================================================
// K5 (fp16 MMA, cp.async-overlapped residual; y raw fp16 copy; default bounds)
// =============================================================================
#define K5_SMEM ((128 * 72 + 64 * 72) * 2 + 64 * 132 * 4)   // 61440 B

__global__ __launch_bounds__(256) void k5_out(
    const float* __restrict__ x, const float* __restrict__ Ww,
    const float* __restrict__ Wb, float* __restrict__ out)
{
    const int b  = blockIdx.z;
    const int a0 = blockIdx.y * 128;
    const int d0 = blockIdx.x * 64;

    extern __shared__ char sm5[];
    __half* As = (__half*)sm5;
    __half* Bs = As + 128 * 72;
    float*  Xs = (float*)(sm5 + (128 * 72 + 64 * 72) * 2);

    const int tid = threadIdx.x;
    const int wid = tid >> 5, lane = tid & 31;
    const int grp = lane >> 2, tig = lane & 3;
    const int wa = wid >> 1, wd = wid & 1;

    const float* xb = x + (size_t)b * NC * NC;
    const uint32_t xs_base = smemU32(Xs);

#pragma unroll
    for (int p = 0; p < 8; p++) {
        int slot = tid + p * 256;
        int dl = slot >> 5, q = slot & 31;
        const float* src = xb + (size_t)(d0 + dl) * NC + a0 + q * 4;
        uint32_t dst = xs_base + (uint32_t)(dl * 132 + q * 4) * 4;
        asm volatile("cp.async.cg.shared.global [%0], [%1], 16;" :: "r"(dst), "l"(src));
    }
    asm volatile("cp.async.commit_group;");

#pragma unroll
    for (int p = 0; p < 8; p++) {
        int slot = tid + p * 256;
        int r = slot >> 4, q = slot & 15;
        float4 v = *(const float4*)(Ww + (size_t)(a0 + r) * NI + q * 4);
        uint32_t* d = (uint32_t*)(As + r * 72 + q * 4);
        d[0] = packh2(v.x, v.y); d[1] = packh2(v.z, v.w);
    }
    {
        const __half* yb = d_y16 + ((size_t)b * NC + d0) * NI;
#pragma unroll
        for (int p = 0; p < 2; p++) {
            int slot = tid + p * 256;
            int r = slot >> 3, q = slot & 7;
            *(uint4*)(Bs + r * 72 + q * 8) = *(const uint4*)(yb + (size_t)r * NI + q * 8);
        }
    }
    __syncthreads();

    const uint32_t a_base = smemU32(As);
    const uint32_t b_base = smemU32(Bs);
    float acc[2][4][4];
#pragma unroll
    for (int mf = 0; mf < 2; mf++)
#pragma unroll
        for (int nf = 0; nf < 4; nf++)
#pragma unroll
            for (int j = 0; j < 4; j++) acc[mf][nf][j] = 0.f;

#pragma unroll
    for (int ks = 0; ks < 4; ks++) {
        uint32_t a[2][4];
#pragma unroll
        for (int mf = 0; mf < 2; mf++) {
            uint32_t addr = a_base +
                (uint32_t)(wa * 32 + mf * 16 + (lane & 7) + ((lane >> 3) & 1) * 8) * 144
                + ks * 32 + ((lane >> 4) & 1) * 16;
            ldsm4(a[mf][0], a[mf][1], a[mf][2], a[mf][3], addr);
        }
#pragma unroll
        for (int nf2 = 0; nf2 < 2; nf2++) {
            uint32_t r0, r1, r2, r3;
            uint32_t addr = b_base +
                (uint32_t)(wd * 32 + nf2 * 16 + (lane & 7) + ((lane >> 4) & 1) * 8) * 144
                + ks * 32 + ((lane >> 3) & 1) * 16;
            ldsm4(r0, r1, r2, r3, addr);
            uint32_t b0[2] = { r0, r1 }, b1[2] = { r2, r3 };
#pragma unroll
            for (int mf = 0; mf < 2; mf++) {
                mma16h(acc[mf][2 * nf2],     a[mf], b0);
                mma16h(acc[mf][2 * nf2 + 1], a[mf], b1);
            }
        }
    }

    asm volatile("cp.async.wait_group 0;");
    __syncthreads();

    float* ob = out + (size_t)b * NC * NC;
#pragma unroll
    for (int mf = 0; mf < 2; mf++)
#pragma unroll
        for (int h = 0; h < 2; h++) {
            int al = wa * 32 + mf * 16 + grp + 8 * h;
            int a  = a0 + al;
            float wb_ = Wb[a];
#pragma unroll
            for (int nf = 0; nf < 4; nf++) {
                int d = wd * 32 + nf * 8 + tig * 2;
                float r0 = Xs[d * 132 + al];
                float r1 = Xs[(d + 1) * 132 + al];
                *(float2*)(ob + (size_t)a * NC + d0 + d) =
                    make_float2(acc[mf][nf][2 * h] + wb_ + r0,
                                acc[mf][nf][2 * h + 1] + wb_ + r1);
            }
        }
}

// =============================================================================
extern "C" void kernel_launch(void* const* d_in, const int* in_sizes, int n_in,
                              void* d_out, int out_size)
{
    (void)in_sizes; (void)n_in; (void)out_size;
    const float* x   = (const float*)d_in[0];
    const float* g_w = (const float*)d_in[1];
    const float* g_b = (const float*)d_in[2];
    const float* t_w = (const float*)d_in[3];
    const float* t_b = (const float*)d_in[4];
    const float* p_w = (const float*)d_in[5];
    const float* p_b = (const float*)d_in[6];
    const float* W_w = (const float*)d_in[7];
    const float* W_b = (const float*)d_in[8];
    float* out = (float*)d_out;

    static int attr_set = 0;
    if (!attr_set) {
        cudaFuncSetAttribute(k2_stats, cudaFuncAttributeMaxDynamicSharedMemorySize, K2_SMEM);
        cudaFuncSetAttribute(k4_fused, cudaFuncAttributeMaxDynamicSharedMemorySize, K4_SMEM);
        cudaFuncSetAttribute(k5_out, cudaFuncAttributeMaxDynamicSharedMemorySize, K5_SMEM);
        attr_set = 1;
    }

    k0_prep  <<<3 * NI * NC / 4 / 256, 256>>>(t_w, p_w, g_w);
    k1_proj  <<<dim3(NC / 128, BATCH), 256>>>(x, t_b, p_b, g_b);
    k2_stats <<<dim3(NC / 128, BATCH), 256, K2_SMEM>>>();
    k3b_stats<<<BATCH * NC / 256, 256>>>();
    k4_fused <<<dim3(NC / 128, BATCH), 256, K4_SMEM>>>();
    k5_out   <<<dim3(NC / 64, NC / 128, BATCH), 256, K5_SMEM>>>(x, W_w, W_b, out);
}